// round 16
// baseline (speedup 1.0000x reference)
#include <cuda_runtime.h>
#include <cuda_fp16.h>
#include <cstdint>

// ---------------------------------------------------------------------------
// QuantizedLMHead (sm_103 baseline ISA):
//   prep A: x -> xh + 2^-11*xl', U -> Uh + 2^-11*Ul'   (small standalone)
//   GEMM1 (hybrid grid): tiles [0,512) scaled-residual 3-pass + quantize;
//     blocks [512,8512): Wh = fp16((lx*lw)*Z_w) backfill (wave-tail absorbed)
//   GEMM2: logits = A @ Wh — PERSISTENT grid-stride CTAs with cross-tile
//     prefetch: last 2 kt of each tile load the next tile's stage 0/1, so the
//     cp.async pipeline never drains at tile boundaries. mma order per tile
//     unchanged -> bitwise-identical numerics.
// ---------------------------------------------------------------------------

#define D_DIM 2048
#define V_DIM 32000
#define N_TOK 4096
#define RES_SCALE 2048.0f
#define RES_INV   (1.0f / 2048.0f)

#define G1_TILES 512                 // 32 (m) x 16 (n)
#define WPREP_BLOCKS 8000
#define G2_TILES 8000                // 32 (m) x 250 (n)

__device__ __align__(256) __half g_Aq[(size_t)N_TOK * D_DIM];   // 16.8 MB
__device__ __align__(256) __half g_Wx[(size_t)D_DIM * V_DIM];   // 131 MB
__device__ __align__(256) __half g_xh[(size_t)N_TOK * D_DIM];
__device__ __align__(256) __half g_xl[(size_t)N_TOK * D_DIM];   // scaled 2^11
__device__ __align__(256) __half g_Uh[(size_t)D_DIM * D_DIM];
__device__ __align__(256) __half g_Ul[(size_t)D_DIM * D_DIM];   // scaled 2^11

// ---------------- PTX helpers ----------------------------------------------
__device__ __forceinline__ uint32_t smem_u32(const void* p) {
    uint32_t a;
    asm("{ .reg .u64 t; cvta.to.shared.u64 t, %1; cvt.u32.u64 %0, t; }" : "=r"(a) : "l"(p));
    return a;
}
__device__ __forceinline__ void cp16(uint32_t dst, const void* src) {
    asm volatile("cp.async.cg.shared.global [%0], [%1], 16;" :: "r"(dst), "l"(src));
}
#define CP_COMMIT() asm volatile("cp.async.commit_group;" ::: "memory")
#define CP_WAIT1()  asm volatile("cp.async.wait_group 1;" ::: "memory")

__device__ __forceinline__ void ldsm4(uint32_t* r, uint32_t addr) {
    asm volatile("ldmatrix.sync.aligned.m8n8.x4.shared.b16 {%0,%1,%2,%3}, [%4];"
                 : "=r"(r[0]), "=r"(r[1]), "=r"(r[2]), "=r"(r[3]) : "r"(addr));
}
__device__ __forceinline__ void ldsm4t(uint32_t* r, uint32_t addr) {
    asm volatile("ldmatrix.sync.aligned.m8n8.x4.trans.shared.b16 {%0,%1,%2,%3}, [%4];"
                 : "=r"(r[0]), "=r"(r[1]), "=r"(r[2]), "=r"(r[3]) : "r"(addr));
}
__device__ __forceinline__ void mma16816(float* c, const uint32_t* a, uint32_t b0, uint32_t b1) {
    asm volatile("mma.sync.aligned.m16n8k16.row.col.f32.f16.f16.f32 "
                 "{%0,%1,%2,%3}, {%4,%5,%6,%7}, {%8,%9}, {%0,%1,%2,%3};"
                 : "+f"(c[0]), "+f"(c[1]), "+f"(c[2]), "+f"(c[3])
                 : "r"(a[0]), "r"(a[1]), "r"(a[2]), "r"(a[3]), "r"(b0), "r"(b1));
}

// ---------------------------------------------------------------------------
// Prep A kernel: x/U hi-lo splits only.
// ---------------------------------------------------------------------------
#define SPLITX_BLKS 4096
#define SPLITU_BLKS 2048
#define SPLIT_BLKS  (SPLITX_BLKS + SPLITU_BLKS)

__device__ __forceinline__ void split8(const float* __restrict__ src, size_t i8,
                                       __half* __restrict__ hi, __half* __restrict__ lo)
{
    float4 v0 = *reinterpret_cast<const float4*>(src + i8);
    float4 v1 = *reinterpret_cast<const float4*>(src + i8 + 4);
    const float f[8] = {v0.x, v0.y, v0.z, v0.w, v1.x, v1.y, v1.z, v1.w};
    __half h[8], l[8];
    #pragma unroll
    for (int j = 0; j < 8; ++j) {
        h[j] = __float2half(f[j]);
        l[j] = __float2half((f[j] - __half2float(h[j])) * RES_SCALE);
    }
    *reinterpret_cast<uint4*>(hi + i8) = *reinterpret_cast<const uint4*>(h);
    *reinterpret_cast<uint4*>(lo + i8) = *reinterpret_cast<const uint4*>(l);
}

__global__ __launch_bounds__(256)
void prep_xu_kernel(const float* __restrict__ x, const float* __restrict__ U)
{
    const int b = blockIdx.x;
    if (b < SPLITX_BLKS) {
        const size_t i8 = ((size_t)b * 256 + threadIdx.x) * 8;
        split8(x, i8, g_xh, g_xl);
    } else {
        const size_t i8 = ((size_t)(b - SPLITX_BLKS) * 256 + threadIdx.x) * 8;
        split8(U, i8, g_Uh, g_Ul);
    }
}

// ---------------------------------------------------------------------------
// GEMM tiling: 128x128 CTA tile, BK=64, 3-stage cp.async, 2 CTAs/SM.
// 256 threads = 8 warps as 2(m)x4(n), warp tile 64x32.
// ---------------------------------------------------------------------------
#define BKK 64
#define STAGES 3
#define A_ROW_B 144
#define B_ROW_B 272
#define A_STG (128 * A_ROW_B)           // 18432
#define B_STG (64 * B_ROW_B)            // 17408
#define STG_B (A_STG + B_STG)           // 35840
#define SMEM_MMA (STAGES * STG_B)       // 107520 -> 2 CTAs/SM
#define NTHREADS 256

// ---------------------------------------------------------------------------
// GEMM1 hybrid — tiles + Wh-prep backfill blocks.  (R14-proven, unchanged)
// ---------------------------------------------------------------------------
__global__ __launch_bounds__(NTHREADS, 2)
void gemm1_mma_kernel(const float* __restrict__ lx, const float* __restrict__ cb,
                      const float* __restrict__ Zw, const float* __restrict__ lw)
{
    const int b = blockIdx.x;

    if (b >= G1_TILES) {
        const uint32_t base = (uint32_t)(b - G1_TILES) * 8192u;
        #pragma unroll
        for (int i = 0; i < 8; ++i) {
            const uint32_t e = base + ((uint32_t)i * 256u + threadIdx.x) * 4u;
            const uint32_t k = e / (uint32_t)V_DIM;
            const float coeff = __ldg(lx + k) * __ldg(lw + k);
            float4 v = *reinterpret_cast<const float4*>(Zw + e);
            __half h[4];
            h[0] = __float2half(coeff * v.x);
            h[1] = __float2half(coeff * v.y);
            h[2] = __float2half(coeff * v.z);
            h[3] = __float2half(coeff * v.w);
            *reinterpret_cast<uint2*>(g_Wx + e) = *reinterpret_cast<const uint2*>(h);
        }
        return;
    }

    extern __shared__ __align__(128) unsigned char sm1[];
    const uint32_t sb = smem_u32(sm1);
    const int tid  = threadIdx.x;
    const int lane = tid & 31;
    const int wid  = tid >> 5;
    const int wm   = wid >> 2;
    const int wn   = wid & 3;
    const int m0   = (b & 31) * 128;
    const int n0   = (b >> 5) * 128;

    float acc[4][4][4];
    #pragma unroll
    for (int mi = 0; mi < 4; ++mi)
        #pragma unroll
        for (int ni = 0; ni < 4; ++ni)
            #pragma unroll
            for (int r = 0; r < 4; ++r) acc[mi][ni][r] = 0.0f;

    auto load_stage = [&](int kt, int slot) {
        const int p  = kt >> 5;
        const int kb = (kt & 31) * BKK;
        const __half* Ab = (p == 0) ? g_xl : g_xh;
        const __half* Bb = (p == 1) ? g_Ul : g_Uh;
        const uint32_t sa  = sb + slot * STG_B;
        const uint32_t sbB = sa + A_STG;
        #pragma unroll
        for (int i = 0; i < 4; ++i) {
            int cc = tid + i * NTHREADS;
            int row = cc >> 3, col = (cc & 7) * 8;
            cp16(sa + row * A_ROW_B + col * 2,
                 Ab + (size_t)(m0 + row) * D_DIM + kb + col);
        }
        #pragma unroll
        for (int i = 0; i < 4; ++i) {
            int cc = tid + i * NTHREADS;
            int row = cc >> 4, col = (cc & 15) * 8;
            cp16(sbB + row * B_ROW_B + col * 2,
                 Bb + (size_t)(kb + row) * D_DIM + n0 + col);
        }
        CP_COMMIT();
    };

    const int KT = 3 * (D_DIM / BKK);    // 96
    load_stage(0, 0);
    load_stage(1, 1);

    const int a_row_l = wm * 64 + (lane & 15);
    const int a_k_l   = (lane >> 4) * 8;
    const int b_row_l = (lane & 7) + ((lane >> 3) & 1) * 8;
    const int b_col_l = wn * 32 + ((lane >> 4) & 1) * 8;

    int slot = 0;
    for (int kt = 0; kt < KT; ++kt) {
        if (kt == 64) {
            #pragma unroll
            for (int mi = 0; mi < 4; ++mi)
                #pragma unroll
                for (int ni = 0; ni < 4; ++ni)
                    #pragma unroll
                    for (int r = 0; r < 4; ++r)
                        acc[mi][ni][r] *= RES_INV;
        }

        CP_WAIT1();
        __syncthreads();
        const uint32_t sa  = sb + slot * STG_B;
        const uint32_t sbb = sa + A_STG;

        #pragma unroll
        for (int ks = 0; ks < 4; ++ks) {
            uint32_t a[4][4], bfr[2][4];
            #pragma unroll
            for (int mi = 0; mi < 4; ++mi)
                ldsm4(a[mi], sa + (a_row_l + mi * 16) * A_ROW_B + (a_k_l + ks * 16) * 2);
            #pragma unroll
            for (int ni2 = 0; ni2 < 2; ++ni2)
                ldsm4t(bfr[ni2], sbb + (b_row_l + ks * 16) * B_ROW_B + (b_col_l + ni2 * 16) * 2);
            #pragma unroll
            for (int mi = 0; mi < 4; ++mi)
                #pragma unroll
                for (int ni = 0; ni < 4; ++ni)
                    mma16816(acc[mi][ni], a[mi], bfr[ni >> 1][2 * (ni & 1)],
                             bfr[ni >> 1][2 * (ni & 1) + 1]);
        }

        if (kt + 2 < KT) load_stage(kt + 2, (slot + 2) % STAGES);
        else CP_COMMIT();
        slot = (slot + 1) % STAGES;
    }

    float c[16];
    #pragma unroll
    for (int t = 0; t < 16; ++t) c[t] = cb[t];

    #pragma unroll
    for (int ni = 0; ni < 4; ++ni) {
        const int c0 = n0 + wn * 32 + ni * 8 + (lane & 3) * 2;
        float l0 = lx[c0], l1 = lx[c0 + 1];
        float s0 = (fabsf(l0) < 1e-8f) ? 1e-8f : l0;
        float s1 = (fabsf(l1) < 1e-8f) ? 1e-8f : l1;
        #pragma unroll
        for (int mi = 0; mi < 4; ++mi) {
            const int r0 = m0 + wm * 64 + mi * 16 + (lane >> 2);
            #pragma unroll
            for (int half_i = 0; half_i < 2; ++half_i) {
                float z0 = acc[mi][ni][2 * half_i]     / s0;
                float z1 = acc[mi][ni][2 * half_i + 1] / s1;
                float q0 = c[0], q1 = c[0];
                #pragma unroll
                for (int t = 0; t < 15; ++t) {
                    float mid = 0.5f * (c[t] + c[t + 1]);
                    q0 = (z0 > mid) ? c[t + 1] : q0;
                    q1 = (z1 > mid) ? c[t + 1] : q1;
                }
                __half2 hv = __halves2half2(__float2half(q0), __float2half(q1));
                *reinterpret_cast<uint32_t*>(
                    &g_Aq[(size_t)(r0 + 8 * half_i) * D_DIM + c0]) =
                    *reinterpret_cast<uint32_t*>(&hv);
            }
        }
    }
}

// ---------------------------------------------------------------------------
// GEMM2 — persistent grid-stride with cross-tile prefetch. K = 2048.
// grid = 2 * numSMs CTAs; tile = blockIdx.x + k*gridDim.x.
// ---------------------------------------------------------------------------
__global__ __launch_bounds__(NTHREADS, 2)
void gemm2_mma_kernel(float* __restrict__ C)
{
    extern __shared__ __align__(128) unsigned char sm2[];
    const uint32_t sb = smem_u32(sm2);
    const int tid  = threadIdx.x;
    const int lane = tid & 31;
    const int wid  = tid >> 5;
    const int wm   = wid >> 2;
    const int wn   = wid & 3;
    const int gstride = gridDim.x;

    const int a_row_l = wm * 64 + (lane & 15);
    const int a_k_l   = (lane >> 4) * 8;
    const int b_row_l = (lane & 7) + ((lane >> 3) & 1) * 8;
    const int b_col_l = wn * 32 + ((lane >> 4) & 1) * 8;

    auto load_stage = [&](int m0_, int n0_, int kt, int slot) {
        const int kb = kt * BKK;
        const uint32_t sa  = sb + slot * STG_B;
        const uint32_t sbB = sa + A_STG;
        #pragma unroll
        for (int i = 0; i < 4; ++i) {
            int cc = tid + i * NTHREADS;
            int row = cc >> 3, col = (cc & 7) * 8;
            cp16(sa + row * A_ROW_B + col * 2,
                 g_Aq + (size_t)(m0_ + row) * D_DIM + kb + col);
        }
        #pragma unroll
        for (int i = 0; i < 4; ++i) {
            int cc = tid + i * NTHREADS;
            int row = cc >> 4, col = (cc & 15) * 8;
            cp16(sbB + row * B_ROW_B + col * 2,
                 g_Wx + (size_t)(kb + row) * V_DIM + n0_ + col);
        }
        CP_COMMIT();
    };

    const int KT = D_DIM / BKK;     // 32

    int tile = blockIdx.x;
    if (tile >= G2_TILES) return;
    int m0 = (tile & 31) * 128;
    int n0 = (tile >> 5) * 128;

    int slot = 0;
    load_stage(m0, n0, 0, 0);
    load_stage(m0, n0, 1, 1);

    for (;;) {
        const int ntile = tile + gstride;
        const bool has_next = (ntile < G2_TILES);
        const int nm0 = (ntile & 31) * 128;
        const int nn0 = (ntile >> 5) * 128;

        float acc[4][4][4];
        #pragma unroll
        for (int mi = 0; mi < 4; ++mi)
            #pragma unroll
            for (int ni = 0; ni < 4; ++ni)
                #pragma unroll
                for (int r = 0; r < 4; ++r) acc[mi][ni][r] = 0.0f;

        for (int kt = 0; kt < KT; ++kt) {
            CP_WAIT1();
            __syncthreads();
            const uint32_t sa  = sb + slot * STG_B;
            const uint32_t sbb = sa + A_STG;

            #pragma unroll
            for (int ks = 0; ks < 4; ++ks) {
                uint32_t a[4][4], bfr[2][4];
                #pragma unroll
                for (int mi = 0; mi < 4; ++mi)
                    ldsm4(a[mi], sa + (a_row_l + mi * 16) * A_ROW_B + (a_k_l + ks * 16) * 2);
                #pragma unroll
                for (int ni2 = 0; ni2 < 2; ++ni2)
                    ldsm4t(bfr[ni2], sbb + (b_row_l + ks * 16) * B_ROW_B + (b_col_l + ni2 * 16) * 2);
                #pragma unroll
                for (int mi = 0; mi < 4; ++mi)
                    #pragma unroll
                    for (int ni = 0; ni < 4; ++ni)
                        mma16816(acc[mi][ni], a[mi], bfr[ni >> 1][2 * (ni & 1)],
                                 bfr[ni >> 1][2 * (ni & 1) + 1]);
            }

            const int pf = kt + 2;
            if (pf < KT)            load_stage(m0, n0, pf, (slot + 2) % STAGES);
            else if (has_next)      load_stage(nm0, nn0, pf - KT, (slot + 2) % STAGES);
            else                    CP_COMMIT();
            slot = (slot + 1) % STAGES;
        }

        // epilogue (next tile's stage 0/1 already in flight)
        #pragma unroll
        for (int mi = 0; mi < 4; ++mi) {
            const int row = m0 + wm * 64 + mi * 16 + (lane >> 2);
            #pragma unroll
            for (int ni = 0; ni < 4; ++ni) {
                const int col = n0 + wn * 32 + ni * 8 + (lane & 3) * 2;
                float2 v0 = make_float2(acc[mi][ni][0], acc[mi][ni][1]);
                float2 v1 = make_float2(acc[mi][ni][2], acc[mi][ni][3]);
                *reinterpret_cast<float2*>(C + (size_t)row * V_DIM + col) = v0;
                *reinterpret_cast<float2*>(C + (size_t)(row + 8) * V_DIM + col) = v1;
            }
        }

        if (!has_next) break;
        tile = ntile; m0 = nm0; n0 = nn0;
    }
}

// ---------------------------------------------------------------------------
extern "C" void kernel_launch(void* const* d_in, const int* in_sizes, int n_in,
                              void* d_out, int out_size)
{
    const float* x  = (const float*)d_in[0];
    const float* U  = (const float*)d_in[1];
    const float* lx = (const float*)d_in[2];
    const float* lw = (const float*)d_in[3];
    const float* Zw = (const float*)d_in[4];
    const float* cb = (const float*)d_in[5];
    float* out = (float*)d_out;

    cudaFuncSetAttribute(gemm1_mma_kernel,
                         cudaFuncAttributeMaxDynamicSharedMemorySize, SMEM_MMA);
    cudaFuncSetAttribute(gemm2_mma_kernel,
                         cudaFuncAttributeMaxDynamicSharedMemorySize, SMEM_MMA);

    int nsm = 0;
    cudaDeviceGetAttribute(&nsm, cudaDevAttrMultiProcessorCount, 0);
    const int g2_grid = 2 * nsm;   // persistent: exactly resident (2 CTAs/SM)

    // 1) x/U hi-lo splits (gemm1 dependency)
    prep_xu_kernel<<<SPLIT_BLKS, 256>>>(x, U);

    // 2) GEMM1 tiles + Wh-prep backfill in one grid
    gemm1_mma_kernel<<<G1_TILES + WPREP_BLOCKS, NTHREADS, SMEM_MMA>>>(lx, cb, Zw, lw);

    // 3) GEMM2 persistent -> logits
    gemm2_mma_kernel<<<g2_grid, NTHREADS, SMEM_MMA>>>(out);
}